// round 1
// baseline (speedup 1.0000x reference)
#include <cuda_runtime.h>
#include <math.h>

// Problem constants
constexpr int Bb = 2;
constexpr int Ss = 2048;
constexpr int Dd = 1024;
constexpr int Hh = 16;
constexpr int DK = 64;
constexpr int Mrows = Bb * Ss;           // 4096
constexpr float SCALE = 0.125f;          // 1/sqrt(64)

// Scratch (device globals — no allocation allowed)
__device__ float g_Q[(size_t)Bb * Hh * Ss * DK];   // [B,H,S,DK]
__device__ float g_K[(size_t)Bb * Hh * Ss * DK];
__device__ float g_V[(size_t)Bb * Hh * Ss * DK];
__device__ float g_O[(size_t)Bb * Ss * Dd];        // [B,S,D] head-merged

// ---------------------------------------------------------------------------
// SGEMM: C[M,N] = A[M,K] * W[K,N], fp32, 128x128x16 tiles, 256 thr, 8x8/thread
// WRITE_MODE 0: plain row-major C
// WRITE_MODE 1: split-head write: m=(b,s), n=(h,dk) -> C[((b*H+h)*S+s)*DK+dk]
// ---------------------------------------------------------------------------
template <int WRITE_MODE>
__global__ __launch_bounds__(256)
void sgemm_kernel(const float* __restrict__ A, const float* __restrict__ W,
                  float* __restrict__ C, int M, int N, int K) {
    __shared__ float As[16][128];   // transposed: As[k][m]
    __shared__ float Bs[16][128];   // natural:    Bs[k][n]

    const int tid = threadIdx.x;
    const int bm = blockIdx.y * 128;
    const int bn = blockIdx.x * 128;

    // A-tile load mapping: 128 rows x 16 cols, float4 along K
    const int aRow = tid >> 2;             // 0..63
    const int aCol = (tid & 3) * 4;        // 0,4,8,12
    // B-tile load mapping: 16 rows x 128 cols, float4 along N
    const int bRow = tid >> 5;             // 0..7
    const int bCol = (tid & 31) * 4;

    const int tr = (tid >> 4) * 8;         // output row base within tile
    const int tc = (tid & 15) * 8;         // output col base within tile

    float acc[8][8];
#pragma unroll
    for (int i = 0; i < 8; i++)
#pragma unroll
        for (int j = 0; j < 8; j++) acc[i][j] = 0.0f;

    for (int k0 = 0; k0 < K; k0 += 16) {
#pragma unroll
        for (int p = 0; p < 2; p++) {
            int r = aRow + p * 64;
            float4 v = *(const float4*)(A + (size_t)(bm + r) * K + k0 + aCol);
            As[aCol + 0][r] = v.x;
            As[aCol + 1][r] = v.y;
            As[aCol + 2][r] = v.z;
            As[aCol + 3][r] = v.w;
        }
#pragma unroll
        for (int p = 0; p < 2; p++) {
            int r = bRow + p * 8;
            *(float4*)(&Bs[r][bCol]) =
                *(const float4*)(W + (size_t)(k0 + r) * N + bn + bCol);
        }
        __syncthreads();

#pragma unroll
        for (int kk = 0; kk < 16; kk++) {
            float ra[8], rb[8];
            *(float4*)(&ra[0]) = *(const float4*)(&As[kk][tr]);
            *(float4*)(&ra[4]) = *(const float4*)(&As[kk][tr + 4]);
            *(float4*)(&rb[0]) = *(const float4*)(&Bs[kk][tc]);
            *(float4*)(&rb[4]) = *(const float4*)(&Bs[kk][tc + 4]);
#pragma unroll
            for (int i = 0; i < 8; i++)
#pragma unroll
                for (int j = 0; j < 8; j++) acc[i][j] = fmaf(ra[i], rb[j], acc[i][j]);
        }
        __syncthreads();
    }

    if (WRITE_MODE == 0) {
#pragma unroll
        for (int i = 0; i < 8; i++) {
            int m = bm + tr + i;
            *(float4*)(C + (size_t)m * N + bn + tc)     = *(float4*)(&acc[i][0]);
            *(float4*)(C + (size_t)m * N + bn + tc + 4) = *(float4*)(&acc[i][4]);
        }
    } else {
#pragma unroll
        for (int i = 0; i < 8; i++) {
            int m = bm + tr + i;
            int b = m / Ss, s = m % Ss;
#pragma unroll
            for (int j = 0; j < 8; j++) {
                int n = bn + tc + j;
                int h = n / DK, dk = n % DK;
                C[(((size_t)(b * Hh + h)) * Ss + s) * DK + dk] = acc[i][j];
            }
        }
    }
}

// ---------------------------------------------------------------------------
// Flash attention: one CTA per (bh, 64-row Q tile). 256 threads (16x16),
// each thread owns a 4x4 micro-tile. Online softmax over 32 K/V tiles of 64.
// ---------------------------------------------------------------------------
constexpr int ATTN_SMEM_FLOATS = 64 * 64 + 64 * 65 + 64 * 64 + 64 * 64; // Q,Kt,V,P
constexpr int ATTN_SMEM_BYTES = ATTN_SMEM_FLOATS * 4;                   // 65792

__global__ __launch_bounds__(256)
void attn_kernel() {
    extern __shared__ float sm[];
    float* Qs  = sm;                 // [64][64]
    float* Kts = Qs + 64 * 64;       // [64][65] transposed: Kts[d][token]
    float* Vs  = Kts + 64 * 65;      // [64][64]
    float* Ps  = Vs + 64 * 64;       // [64][64]

    const int bh = blockIdx.y;       // b*H + h
    const int qt = blockIdx.x;       // q tile index
    const int tid = threadIdx.x;
    const int ty = tid >> 4;         // 0..15 (row group)
    const int tx = tid & 15;         // 0..15 (col group)

    const float* Qg = g_Q + (size_t)bh * Ss * DK;
    const float* Kg = g_K + (size_t)bh * Ss * DK;
    const float* Vg = g_V + (size_t)bh * Ss * DK;

    // Load Q tile (coalesced float4)
#pragma unroll
    for (int p = 0; p < 4; p++) {
        int f = tid + p * 256;           // float4 index, 0..1023
        int row = f >> 4;
        int col = (f & 15) * 4;
        *(float4*)(&Qs[row * 64 + col]) =
            *(const float4*)(Qg + (size_t)(qt * 64 + row) * DK + col);
    }

    float m_run[4], l_run[4], acc[4][4];
#pragma unroll
    for (int i = 0; i < 4; i++) {
        m_run[i] = -1e30f;
        l_run[i] = 0.0f;
#pragma unroll
        for (int j = 0; j < 4; j++) acc[i][j] = 0.0f;
    }

    for (int kt = 0; kt < Ss / 64; kt++) {
        __syncthreads();  // previous PV done before overwriting K/V/P

        // Load K tile transposed, V tile natural
#pragma unroll
        for (int p = 0; p < 4; p++) {
            int f = tid + p * 256;
            int row = f >> 4;
            int col = (f & 15) * 4;
            float4 kv = *(const float4*)(Kg + (size_t)(kt * 64 + row) * DK + col);
            Kts[(col + 0) * 65 + row] = kv.x;
            Kts[(col + 1) * 65 + row] = kv.y;
            Kts[(col + 2) * 65 + row] = kv.z;
            Kts[(col + 3) * 65 + row] = kv.w;
            *(float4*)(&Vs[row * 64 + col]) =
                *(const float4*)(Vg + (size_t)(kt * 64 + row) * DK + col);
        }
        __syncthreads();

        // S = (Q K^T) * SCALE, 4x4 per thread
        float s[4][4];
#pragma unroll
        for (int i = 0; i < 4; i++)
#pragma unroll
            for (int j = 0; j < 4; j++) s[i][j] = 0.0f;

#pragma unroll 8
        for (int kk = 0; kk < 64; kk++) {
            float a[4], kb[4];
#pragma unroll
            for (int i = 0; i < 4; i++) a[i] = Qs[(ty * 4 + i) * 64 + kk];
#pragma unroll
            for (int j = 0; j < 4; j++) kb[j] = Kts[kk * 65 + tx * 4 + j];
#pragma unroll
            for (int i = 0; i < 4; i++)
#pragma unroll
                for (int j = 0; j < 4; j++) s[i][j] = fmaf(a[i], kb[j], s[i][j]);
        }

        // Online softmax update per row
#pragma unroll
        for (int i = 0; i < 4; i++) {
            float mt = -1e30f;
#pragma unroll
            for (int j = 0; j < 4; j++) {
                s[i][j] *= SCALE;
                mt = fmaxf(mt, s[i][j]);
            }
            mt = fmaxf(mt, __shfl_xor_sync(0xffffffffu, mt, 1));
            mt = fmaxf(mt, __shfl_xor_sync(0xffffffffu, mt, 2));
            mt = fmaxf(mt, __shfl_xor_sync(0xffffffffu, mt, 4));
            mt = fmaxf(mt, __shfl_xor_sync(0xffffffffu, mt, 8));

            float mnew = fmaxf(m_run[i], mt);
            float alpha = __expf(m_run[i] - mnew);
            float rs = 0.0f;
#pragma unroll
            for (int j = 0; j < 4; j++) {
                float p = __expf(s[i][j] - mnew);
                s[i][j] = p;
                rs += p;
            }
            rs += __shfl_xor_sync(0xffffffffu, rs, 1);
            rs += __shfl_xor_sync(0xffffffffu, rs, 2);
            rs += __shfl_xor_sync(0xffffffffu, rs, 4);
            rs += __shfl_xor_sync(0xffffffffu, rs, 8);

            l_run[i] = l_run[i] * alpha + rs;
            m_run[i] = mnew;
#pragma unroll
            for (int j = 0; j < 4; j++) acc[i][j] *= alpha;
            // store P row-chunk
#pragma unroll
            for (int j = 0; j < 4; j++)
                Ps[(ty * 4 + i) * 64 + tx * 4 + j] = s[i][j];
        }
        __syncthreads();

        // O += P @ V
#pragma unroll 8
        for (int c = 0; c < 64; c++) {
            float pr[4];
#pragma unroll
            for (int i = 0; i < 4; i++) pr[i] = Ps[(ty * 4 + i) * 64 + c];
            float4 vv = *(const float4*)(&Vs[c * 64 + tx * 4]);
            float vb[4] = {vv.x, vv.y, vv.z, vv.w};
#pragma unroll
            for (int i = 0; i < 4; i++)
#pragma unroll
                for (int j = 0; j < 4; j++) acc[i][j] = fmaf(pr[i], vb[j], acc[i][j]);
        }
    }

    // Normalize and write head-merged O [B,S,D]
    const int b = bh / Hh;
    const int h = bh % Hh;
#pragma unroll
    for (int i = 0; i < 4; i++) {
        int sg = qt * 64 + ty * 4 + i;
        float inv = 1.0f / l_run[i];
        float4 o;
        o.x = acc[i][0] * inv;
        o.y = acc[i][1] * inv;
        o.z = acc[i][2] * inv;
        o.w = acc[i][3] * inv;
        *(float4*)(&g_O[((size_t)(b * Ss + sg)) * Dd + h * DK + tx * 4]) = o;
    }
}

// ---------------------------------------------------------------------------
// Launch
// ---------------------------------------------------------------------------
extern "C" void kernel_launch(void* const* d_in, const int* in_sizes, int n_in,
                              void* d_out, int out_size) {
    const float* q  = (const float*)d_in[0];
    const float* k  = (const float*)d_in[1];
    const float* v  = (const float*)d_in[2];
    const float* Wq = (const float*)d_in[3];
    const float* Wk = (const float*)d_in[4];
    const float* Wv = (const float*)d_in[5];
    const float* Wo = (const float*)d_in[6];
    float* out = (float*)d_out;

    float *Qp, *Kp, *Vp, *Op;
    cudaGetSymbolAddress((void**)&Qp, g_Q);
    cudaGetSymbolAddress((void**)&Kp, g_K);
    cudaGetSymbolAddress((void**)&Vp, g_V);
    cudaGetSymbolAddress((void**)&Op, g_O);

    cudaFuncSetAttribute(attn_kernel,
                         cudaFuncAttributeMaxDynamicSharedMemorySize,
                         ATTN_SMEM_BYTES);

    dim3 gg(Dd / 128, Mrows / 128);  // (8, 32)
    sgemm_kernel<1><<<gg, 256>>>(q, Wq, Qp, Mrows, Dd, Dd);
    sgemm_kernel<1><<<gg, 256>>>(k, Wk, Kp, Mrows, Dd, Dd);
    sgemm_kernel<1><<<gg, 256>>>(v, Wv, Vp, Mrows, Dd, Dd);

    attn_kernel<<<dim3(Ss / 64, Bb * Hh), 256, ATTN_SMEM_BYTES>>>();

    sgemm_kernel<0><<<gg, 256>>>(Op, Wo, out, Mrows, Dd, Dd);
}

// round 3
// speedup vs baseline: 1.3757x; 1.3757x over previous
#include <cuda_runtime.h>
#include <cuda_bf16.h>
#include <cstdint>
#include <math.h>

// ---------------------------------------------------------------------------
// Problem constants
// ---------------------------------------------------------------------------
constexpr int Bb = 2;
constexpr int Ss = 2048;
constexpr int Dd = 1024;
constexpr int Hh = 16;
constexpr int DK = 64;
constexpr int Mrows = Bb * Ss;           // 4096
constexpr float SCALE = 0.125f;          // 1/sqrt(64)

// ---------------------------------------------------------------------------
// Scratch (device globals)
// ---------------------------------------------------------------------------
__device__ float g_Q[(size_t)Bb * Hh * Ss * DK];
__device__ float g_K[(size_t)Bb * Hh * Ss * DK];
__device__ float g_V[(size_t)Bb * Hh * Ss * DK];
__device__ float g_O[(size_t)Bb * Ss * Dd];

__device__ __nv_bfloat16 g_qhi[(size_t)Mrows * Dd], g_qlo[(size_t)Mrows * Dd];
__device__ __nv_bfloat16 g_khi[(size_t)Mrows * Dd], g_klo[(size_t)Mrows * Dd];
__device__ __nv_bfloat16 g_vhi[(size_t)Mrows * Dd], g_vlo[(size_t)Mrows * Dd];
__device__ __nv_bfloat16 g_ohi[(size_t)Mrows * Dd], g_olo[(size_t)Mrows * Dd];
__device__ __nv_bfloat16 g_whi[4][(size_t)Dd * Dd], g_wlo[4][(size_t)Dd * Dd];

// ---------------------------------------------------------------------------
// mma.sync / ldmatrix / cp.async helpers (plain sm_100-safe PTX)
// ---------------------------------------------------------------------------
__device__ __forceinline__ uint32_t smem_u32(const void* p) {
    uint32_t a;
    asm("{ .reg .u64 t; cvta.to.shared.u64 t, %1; cvt.u32.u64 %0, t; }"
        : "=r"(a) : "l"(p));
    return a;
}

__device__ __forceinline__ void ldm_x4(uint32_t* r, uint32_t addr) {
    asm volatile("ldmatrix.sync.aligned.m8n8.x4.shared.b16 {%0,%1,%2,%3}, [%4];"
                 : "=r"(r[0]), "=r"(r[1]), "=r"(r[2]), "=r"(r[3]) : "r"(addr));
}

__device__ __forceinline__ void mma16816(float* c, const uint32_t* a,
                                         uint32_t b0, uint32_t b1) {
    asm volatile(
        "mma.sync.aligned.m16n8k16.row.col.f32.bf16.bf16.f32 "
        "{%0,%1,%2,%3}, {%4,%5,%6,%7}, {%8,%9}, {%0,%1,%2,%3};"
        : "+f"(c[0]), "+f"(c[1]), "+f"(c[2]), "+f"(c[3])
        : "r"(a[0]), "r"(a[1]), "r"(a[2]), "r"(a[3]), "r"(b0), "r"(b1));
}

__device__ __forceinline__ void cp16(uint32_t dst, const void* src) {
    asm volatile("cp.async.cg.shared.global [%0], [%1], 16;"
                 :: "r"(dst), "l"(src) : "memory");
}
__device__ __forceinline__ void cp_commit() {
    asm volatile("cp.async.commit_group;" ::: "memory");
}
template <int N>
__device__ __forceinline__ void cp_wait() {
    asm volatile("cp.async.wait_group %0;" :: "n"(N) : "memory");
}

// smem tile: 128 rows x 32 bf16, row stride 80B (64B data + 16B pad).
// 80*r mod 128 permutes over 8 consecutive rows -> conflict-free ldmatrix.
constexpr int ROW_B = 80;
constexpr int ARR_B = 128 * ROW_B;       // 10240 per tile
constexpr int BUF_B = 4 * ARR_B;         // Ahi,Alo,Bhi,Blo = 40960
constexpr int GEMM_SMEM_BYTES = 2 * BUF_B;  // 81920

// ldmatrix.x4 lane address: quads (rows r, rows r+8) x (kbyte, kbyte+16)
__device__ __forceinline__ uint32_t frag_addr(uint32_t arr_base, int row0,
                                              int kbyte0, int lane) {
    int r = row0 + ((lane >> 3) & 1) * 8 + (lane & 7);
    int kb = kbyte0 + (lane >> 4) * 16;
    return arr_base + r * ROW_B + kb;
}

// ---------------------------------------------------------------------------
// fp32 -> bf16 hi/lo split, row-major
// ---------------------------------------------------------------------------
__global__ __launch_bounds__(256)
void cvt_split(const float* __restrict__ x, __nv_bfloat16* __restrict__ hi,
               __nv_bfloat16* __restrict__ lo) {
    int i = (blockIdx.x * 256 + threadIdx.x) * 4;
    float4 v = *(const float4*)(x + i);
    float vv[4] = {v.x, v.y, v.z, v.w};
#pragma unroll
    for (int j = 0; j < 4; j++) {
        __nv_bfloat16 h = __float2bfloat16(vv[j]);
        hi[i + j] = h;
        lo[i + j] = __float2bfloat16(vv[j] - __bfloat162float(h));
    }
}

// fp32 W[K,N] -> bf16 hi/lo TRANSPOSED [N,K]
__global__ __launch_bounds__(256)
void cvt_splitT(const float* __restrict__ W, __nv_bfloat16* __restrict__ hiT,
                __nv_bfloat16* __restrict__ loT) {
    __shared__ float t[32][33];
    int tx = threadIdx.x, ty = threadIdx.y;
    int n0 = blockIdx.x * 32, k0 = blockIdx.y * 32;
#pragma unroll
    for (int r = 0; r < 4; r++)
        t[ty + r * 8][tx] = W[(size_t)(k0 + ty + r * 8) * Dd + n0 + tx];
    __syncthreads();
#pragma unroll
    for (int r = 0; r < 4; r++) {
        int n = n0 + ty + r * 8;
        int k = k0 + tx;
        float x = t[tx][ty + r * 8];
        __nv_bfloat16 h = __float2bfloat16(x);
        hiT[(size_t)n * Dd + k] = h;
        loT[(size_t)n * Dd + k] = __float2bfloat16(x - __bfloat162float(h));
    }
}

// ---------------------------------------------------------------------------
// bf16-split tensor-core GEMM via mma.sync:
//   C[4096,1024] = A[M,K] @ B^T   (A,B stored [rows, K] row-major, K=1024)
// CTA tile 128x128, 8 warps (2m x 4n), warp tile 64x32, K-chunk 32,
// cp.async double buffer. 3 MMA products: hi*hi + hi*lo + lo*hi.
// WRITE_MODE 0: row-major C.  WRITE_MODE 1: split-head [B,H,S,DK].
// ---------------------------------------------------------------------------
template <int WRITE_MODE>
__global__ __launch_bounds__(256, 1)
void gemm_bf16split(const __nv_bfloat16* __restrict__ Ahi,
                    const __nv_bfloat16* __restrict__ Alo,
                    const __nv_bfloat16* __restrict__ Bhi,
                    const __nv_bfloat16* __restrict__ Blo,
                    float* __restrict__ C) {
    extern __shared__ char smem[];
    const uint32_t sbase = smem_u32(smem);
    const int tid = threadIdx.x;
    const int lane = tid & 31;
    const int wid = tid >> 5;
    const int wm = wid >> 2;          // 0..1  (m)
    const int wn = wid & 3;           // 0..3  (n)
    const int bm = blockIdx.y * 128;
    const int bn = blockIdx.x * 128;

    const __nv_bfloat16* srcs[4] = {Ahi, Alo, Bhi, Blo};

    // ---- async-load one K-chunk (32 wide) into buffer b: 8 cp.async/thread
    auto load_chunk = [&](int c, int b) {
        const int k0 = c * 32;
        const uint32_t dst0 = sbase + b * BUF_B;
        const int row = tid >> 1;
#pragma unroll
        for (int a4 = 0; a4 < 4; a4++) {
            const __nv_bfloat16* src = srcs[a4];
            const int rbase = (a4 < 2) ? bm : bn;
            const __nv_bfloat16* gsrc =
                src + (size_t)(rbase + row) * Dd + k0;
#pragma unroll
            for (int j = 0; j < 2; j++) {
                int cch = (tid & 1) * 2 + j;
                cp16(dst0 + a4 * ARR_B + row * ROW_B + cch * 16,
                     gsrc + cch * 8);
            }
        }
        cp_commit();
    };

    float acc[4][4][4];   // [m16 frag][n8 frag][c regs]
#pragma unroll
    for (int i = 0; i < 4; i++)
#pragma unroll
        for (int j = 0; j < 4; j++)
#pragma unroll
            for (int r = 0; r < 4; r++) acc[i][j][r] = 0.0f;

    // ---- compute one K-chunk from buffer b
    auto compute = [&](int b) {
        const uint32_t base = sbase + b * BUF_B;
        const uint32_t aHiB = base + 0 * ARR_B;
        const uint32_t aLoB = base + 1 * ARR_B;
        const uint32_t bHiB = base + 2 * ARR_B;
        const uint32_t bLoB = base + 3 * ARR_B;
#pragma unroll
        for (int s = 0; s < 2; s++) {       // two k16 steps
            const int kb = s * 32;          // byte offset of k16 step
            uint32_t ahi[4][4], alo[4][4];
#pragma unroll
            for (int i = 0; i < 4; i++) {
                ldm_x4(ahi[i], frag_addr(aHiB, wm * 64 + i * 16, kb, lane));
                ldm_x4(alo[i], frag_addr(aLoB, wm * 64 + i * 16, kb, lane));
            }
#pragma unroll
            for (int nb = 0; nb < 2; nb++) {  // two n16 blocks
                uint32_t bh[4], bl[4];
                ldm_x4(bh, frag_addr(bHiB, wn * 32 + nb * 16, kb, lane));
                ldm_x4(bl, frag_addr(bLoB, wn * 32 + nb * 16, kb, lane));
                // x4 B regs: {b0 blk0, b0 blk1, b1 blk0, b1 blk1}
#pragma unroll
                for (int i = 0; i < 4; i++) {
                    mma16816(acc[i][nb * 2 + 0], ahi[i], bh[0], bh[2]);
                    mma16816(acc[i][nb * 2 + 1], ahi[i], bh[1], bh[3]);
                    mma16816(acc[i][nb * 2 + 0], ahi[i], bl[0], bl[2]);
                    mma16816(acc[i][nb * 2 + 1], ahi[i], bl[1], bl[3]);
                    mma16816(acc[i][nb * 2 + 0], alo[i], bh[0], bh[2]);
                    mma16816(acc[i][nb * 2 + 1], alo[i], bh[1], bh[3]);
                }
            }
        }
    };

    constexpr int NCHUNK = Dd / 32;    // 32
    load_chunk(0, 0);
    for (int c = 0; c < NCHUNK; c++) {
        if (c + 1 < NCHUNK) {
            load_chunk(c + 1, (c + 1) & 1);
            cp_wait<1>();
        } else {
            cp_wait<0>();
        }
        __syncthreads();
        compute(c & 1);
        __syncthreads();
    }

    // ---- epilogue: acc -> gmem fp32
    const int g = lane >> 2;          // row within 8
    const int tg = lane & 3;          // col pair
#pragma unroll
    for (int i = 0; i < 4; i++) {
        int r0 = bm + wm * 64 + i * 16 + g;
#pragma unroll
        for (int j = 0; j < 4; j++) {
            int col = bn + wn * 32 + j * 8 + tg * 2;
            if (WRITE_MODE == 0) {
                *(float2*)(C + (size_t)r0 * Dd + col) =
                    make_float2(acc[i][j][0], acc[i][j][1]);
                *(float2*)(C + (size_t)(r0 + 8) * Dd + col) =
                    make_float2(acc[i][j][2], acc[i][j][3]);
            } else {
                int h = col >> 6, dk = col & 63;
                int b0_ = r0 >> 11, s0 = r0 & 2047;
                int b1_ = (r0 + 8) >> 11, s1 = (r0 + 8) & 2047;
                *(float2*)(C + (((size_t)(b0_ * Hh + h)) * Ss + s0) * DK + dk) =
                    make_float2(acc[i][j][0], acc[i][j][1]);
                *(float2*)(C + (((size_t)(b1_ * Hh + h)) * Ss + s1) * DK + dk) =
                    make_float2(acc[i][j][2], acc[i][j][3]);
            }
        }
    }
}

// ---------------------------------------------------------------------------
// Flash attention (unchanged from R1): one CTA per (bh, 64-row Q tile).
// ---------------------------------------------------------------------------
constexpr int ATTN_SMEM_FLOATS = 64 * 64 + 64 * 65 + 64 * 64 + 64 * 64;
constexpr int ATTN_SMEM_BYTES = ATTN_SMEM_FLOATS * 4;

__global__ __launch_bounds__(256)
void attn_kernel() {
    extern __shared__ float sm[];
    float* Qs = sm;
    float* Kts = Qs + 64 * 64;
    float* Vs = Kts + 64 * 65;
    float* Ps = Vs + 64 * 64;

    const int bh = blockIdx.y;
    const int qt = blockIdx.x;
    const int tid = threadIdx.x;
    const int ty = tid >> 4;
    const int tx = tid & 15;

    const float* Qg = g_Q + (size_t)bh * Ss * DK;
    const float* Kg = g_K + (size_t)bh * Ss * DK;
    const float* Vg = g_V + (size_t)bh * Ss * DK;

#pragma unroll
    for (int p = 0; p < 4; p++) {
        int f = tid + p * 256;
        int row = f >> 4;
        int col = (f & 15) * 4;
        *(float4*)(&Qs[row * 64 + col]) =
            *(const float4*)(Qg + (size_t)(qt * 64 + row) * DK + col);
    }

    float m_run[4], l_run[4], acc[4][4];
#pragma unroll
    for (int i = 0; i < 4; i++) {
        m_run[i] = -1e30f;
        l_run[i] = 0.0f;
#pragma unroll
        for (int j = 0; j < 4; j++) acc[i][j] = 0.0f;
    }

    for (int kt = 0; kt < Ss / 64; kt++) {
        __syncthreads();
#pragma unroll
        for (int p = 0; p < 4; p++) {
            int f = tid + p * 256;
            int row = f >> 4;
            int col = (f & 15) * 4;
            float4 kv = *(const float4*)(Kg + (size_t)(kt * 64 + row) * DK + col);
            Kts[(col + 0) * 65 + row] = kv.x;
            Kts[(col + 1) * 65 + row] = kv.y;
            Kts[(col + 2) * 65 + row] = kv.z;
            Kts[(col + 3) * 65 + row] = kv.w;
            *(float4*)(&Vs[row * 64 + col]) =
                *(const float4*)(Vg + (size_t)(kt * 64 + row) * DK + col);
        }
        __syncthreads();

        float s[4][4];
#pragma unroll
        for (int i = 0; i < 4; i++)
#pragma unroll
            for (int j = 0; j < 4; j++) s[i][j] = 0.0f;

#pragma unroll 8
        for (int kk = 0; kk < 64; kk++) {
            float a[4], kb[4];
#pragma unroll
            for (int i = 0; i < 4; i++) a[i] = Qs[(ty * 4 + i) * 64 + kk];
#pragma unroll
            for (int j = 0; j < 4; j++) kb[j] = Kts[kk * 65 + tx * 4 + j];
#pragma unroll
            for (int i = 0; i < 4; i++)
#pragma unroll
                for (int j = 0; j < 4; j++) s[i][j] = fmaf(a[i], kb[j], s[i][j]);
        }

#pragma unroll
        for (int i = 0; i < 4; i++) {
            float mt = -1e30f;
#pragma unroll
            for (int j = 0; j < 4; j++) {
                s[i][j] *= SCALE;
                mt = fmaxf(mt, s[i][j]);
            }
            mt = fmaxf(mt, __shfl_xor_sync(0xffffffffu, mt, 1));
            mt = fmaxf(mt, __shfl_xor_sync(0xffffffffu, mt, 2));
            mt = fmaxf(mt, __shfl_xor_sync(0xffffffffu, mt, 4));
            mt = fmaxf(mt, __shfl_xor_sync(0xffffffffu, mt, 8));

            float mnew = fmaxf(m_run[i], mt);
            float alpha = __expf(m_run[i] - mnew);
            float rs = 0.0f;
#pragma unroll
            for (int j = 0; j < 4; j++) {
                float p = __expf(s[i][j] - mnew);
                s[i][j] = p;
                rs += p;
            }
            rs += __shfl_xor_sync(0xffffffffu, rs, 1);
            rs += __shfl_xor_sync(0xffffffffu, rs, 2);
            rs += __shfl_xor_sync(0xffffffffu, rs, 4);
            rs += __shfl_xor_sync(0xffffffffu, rs, 8);

            l_run[i] = l_run[i] * alpha + rs;
            m_run[i] = mnew;
#pragma unroll
            for (int j = 0; j < 4; j++) acc[i][j] *= alpha;
#pragma unroll
            for (int j = 0; j < 4; j++)
                Ps[(ty * 4 + i) * 64 + tx * 4 + j] = s[i][j];
        }
        __syncthreads();

#pragma unroll 8
        for (int c = 0; c < 64; c++) {
            float pr[4];
#pragma unroll
            for (int i = 0; i < 4; i++) pr[i] = Ps[(ty * 4 + i) * 64 + c];
            float4 vv = *(const float4*)(&Vs[c * 64 + tx * 4]);
            float vb[4] = {vv.x, vv.y, vv.z, vv.w};
#pragma unroll
            for (int i = 0; i < 4; i++)
#pragma unroll
                for (int j = 0; j < 4; j++) acc[i][j] = fmaf(pr[i], vb[j], acc[i][j]);
        }
    }

    const int b = bh / Hh;
    const int h = bh % Hh;
#pragma unroll
    for (int i = 0; i < 4; i++) {
        int sg = qt * 64 + ty * 4 + i;
        float inv = 1.0f / l_run[i];
        float4 o;
        o.x = acc[i][0] * inv;
        o.y = acc[i][1] * inv;
        o.z = acc[i][2] * inv;
        o.w = acc[i][3] * inv;
        *(float4*)(&g_O[((size_t)(b * Ss + sg)) * Dd + h * DK + tx * 4]) = o;
    }
}

// ---------------------------------------------------------------------------
// Launch
// ---------------------------------------------------------------------------
extern "C" void kernel_launch(void* const* d_in, const int* in_sizes, int n_in,
                              void* d_out, int out_size) {
    const float* q  = (const float*)d_in[0];
    const float* k  = (const float*)d_in[1];
    const float* v  = (const float*)d_in[2];
    const float* Wq = (const float*)d_in[3];
    const float* Wk = (const float*)d_in[4];
    const float* Wv = (const float*)d_in[5];
    const float* Wo = (const float*)d_in[6];
    float* out = (float*)d_out;

    float *Qp, *Kp, *Vp, *Op;
    cudaGetSymbolAddress((void**)&Qp, g_Q);
    cudaGetSymbolAddress((void**)&Kp, g_K);
    cudaGetSymbolAddress((void**)&Vp, g_V);
    cudaGetSymbolAddress((void**)&Op, g_O);

    __nv_bfloat16 *qhi, *qlo, *khi, *klo, *vhi, *vlo, *ohi, *olo, *whi, *wlo;
    cudaGetSymbolAddress((void**)&qhi, g_qhi);
    cudaGetSymbolAddress((void**)&qlo, g_qlo);
    cudaGetSymbolAddress((void**)&khi, g_khi);
    cudaGetSymbolAddress((void**)&klo, g_klo);
    cudaGetSymbolAddress((void**)&vhi, g_vhi);
    cudaGetSymbolAddress((void**)&vlo, g_vlo);
    cudaGetSymbolAddress((void**)&ohi, g_ohi);
    cudaGetSymbolAddress((void**)&olo, g_olo);
    cudaGetSymbolAddress((void**)&whi, g_whi);
    cudaGetSymbolAddress((void**)&wlo, g_wlo);
    const size_t WSTRIDE = (size_t)Dd * Dd;

    cudaFuncSetAttribute(attn_kernel,
                         cudaFuncAttributeMaxDynamicSharedMemorySize,
                         ATTN_SMEM_BYTES);
    cudaFuncSetAttribute(gemm_bf16split<0>,
                         cudaFuncAttributeMaxDynamicSharedMemorySize,
                         GEMM_SMEM_BYTES);
    cudaFuncSetAttribute(gemm_bf16split<1>,
                         cudaFuncAttributeMaxDynamicSharedMemorySize,
                         GEMM_SMEM_BYTES);

    const int cvt_blocks = Mrows * Dd / (256 * 4);   // 4096
    cvt_split<<<cvt_blocks, 256>>>(q, qhi, qlo);
    cvt_split<<<cvt_blocks, 256>>>(k, khi, klo);
    cvt_split<<<cvt_blocks, 256>>>(v, vhi, vlo);

    dim3 tB(32, 8), tG(Dd / 32, Dd / 32);
    cvt_splitT<<<tG, tB>>>(Wq, whi + 0 * WSTRIDE, wlo + 0 * WSTRIDE);
    cvt_splitT<<<tG, tB>>>(Wk, whi + 1 * WSTRIDE, wlo + 1 * WSTRIDE);
    cvt_splitT<<<tG, tB>>>(Wv, whi + 2 * WSTRIDE, wlo + 2 * WSTRIDE);
    cvt_splitT<<<tG, tB>>>(Wo, whi + 3 * WSTRIDE, wlo + 3 * WSTRIDE);

    dim3 gg(Dd / 128, Mrows / 128);  // (8, 32)
    gemm_bf16split<1><<<gg, 256, GEMM_SMEM_BYTES>>>(qhi, qlo, whi + 0 * WSTRIDE, wlo + 0 * WSTRIDE, Qp);
    gemm_bf16split<1><<<gg, 256, GEMM_SMEM_BYTES>>>(khi, klo, whi + 1 * WSTRIDE, wlo + 1 * WSTRIDE, Kp);
    gemm_bf16split<1><<<gg, 256, GEMM_SMEM_BYTES>>>(vhi, vlo, whi + 2 * WSTRIDE, wlo + 2 * WSTRIDE, Vp);

    attn_kernel<<<dim3(Ss / 64, Bb * Hh), 256, ATTN_SMEM_BYTES>>>();

    cvt_split<<<cvt_blocks, 256>>>(Op, ohi, olo);
    gemm_bf16split<0><<<gg, 256, GEMM_SMEM_BYTES>>>(ohi, olo, whi + 3 * WSTRIDE, wlo + 3 * WSTRIDE, out);
}

// round 4
// speedup vs baseline: 2.3474x; 1.7064x over previous
#include <cuda_runtime.h>
#include <cuda_bf16.h>
#include <cstdint>
#include <math.h>

// ---------------------------------------------------------------------------
// Problem constants
// ---------------------------------------------------------------------------
constexpr int Bb = 2;
constexpr int Ss = 2048;
constexpr int Dd = 1024;
constexpr int Hh = 16;
constexpr int DK = 64;
constexpr int Mrows = Bb * Ss;           // 4096
constexpr float SCALE = 0.125f;          // 1/sqrt(64)

// ---------------------------------------------------------------------------
// Scratch (device globals)
// ---------------------------------------------------------------------------
__device__ __nv_bfloat16 g_qhi[(size_t)Mrows * Dd], g_qlo[(size_t)Mrows * Dd];
__device__ __nv_bfloat16 g_khi[(size_t)Mrows * Dd], g_klo[(size_t)Mrows * Dd];
__device__ __nv_bfloat16 g_vhi[(size_t)Mrows * Dd], g_vlo[(size_t)Mrows * Dd];
__device__ __nv_bfloat16 g_ohi[(size_t)Mrows * Dd], g_olo[(size_t)Mrows * Dd];
__device__ __nv_bfloat16 g_whi[4][(size_t)Dd * Dd], g_wlo[4][(size_t)Dd * Dd];

// split-head projected tensors [bh=32][S=2048][DK=64], bf16 hi/lo
__device__ __nv_bfloat16 g_Qh[(size_t)32 * Ss * DK], g_Ql[(size_t)32 * Ss * DK];
__device__ __nv_bfloat16 g_Kh[(size_t)32 * Ss * DK], g_Kl[(size_t)32 * Ss * DK];
__device__ __nv_bfloat16 g_Vh[(size_t)32 * Ss * DK], g_Vl[(size_t)32 * Ss * DK];

// ---------------------------------------------------------------------------
// mma.sync / ldmatrix / cp.async helpers
// ---------------------------------------------------------------------------
__device__ __forceinline__ uint32_t smem_u32(const void* p) {
    uint32_t a;
    asm("{ .reg .u64 t; cvta.to.shared.u64 t, %1; cvt.u32.u64 %0, t; }"
        : "=r"(a) : "l"(p));
    return a;
}
__device__ __forceinline__ void ldm_x4(uint32_t* r, uint32_t addr) {
    asm volatile("ldmatrix.sync.aligned.m8n8.x4.shared.b16 {%0,%1,%2,%3}, [%4];"
                 : "=r"(r[0]), "=r"(r[1]), "=r"(r[2]), "=r"(r[3]) : "r"(addr));
}
__device__ __forceinline__ void ldm_x4_t(uint32_t* r, uint32_t addr) {
    asm volatile("ldmatrix.sync.aligned.m8n8.x4.trans.shared.b16 {%0,%1,%2,%3}, [%4];"
                 : "=r"(r[0]), "=r"(r[1]), "=r"(r[2]), "=r"(r[3]) : "r"(addr));
}
__device__ __forceinline__ void mma16816(float* c, const uint32_t* a,
                                         uint32_t b0, uint32_t b1) {
    asm volatile(
        "mma.sync.aligned.m16n8k16.row.col.f32.bf16.bf16.f32 "
        "{%0,%1,%2,%3}, {%4,%5,%6,%7}, {%8,%9}, {%0,%1,%2,%3};"
        : "+f"(c[0]), "+f"(c[1]), "+f"(c[2]), "+f"(c[3])
        : "r"(a[0]), "r"(a[1]), "r"(a[2]), "r"(a[3]), "r"(b0), "r"(b1));
}
__device__ __forceinline__ void cp16(uint32_t dst, const void* src) {
    asm volatile("cp.async.cg.shared.global [%0], [%1], 16;"
                 :: "r"(dst), "l"(src) : "memory");
}
__device__ __forceinline__ void cp_commit() {
    asm volatile("cp.async.commit_group;" ::: "memory");
}
template <int N>
__device__ __forceinline__ void cp_wait() {
    asm volatile("cp.async.wait_group %0;" :: "n"(N) : "memory");
}

// A/B fragment address for [rows][red] tiles (non-trans ldmatrix)
template <int ROWB>
__device__ __forceinline__ uint32_t fragA(uint32_t base, int row0, int kb0, int lane) {
    int r = row0 + ((lane >> 3) & 1) * 8 + (lane & 7);
    int kb = kb0 + (lane >> 4) * 16;
    return base + r * ROWB + kb;
}
// trans fragment address: tile [kred rows][n cols]; matrices ordered
// m0=(n0-7,k0-7) m1=(n8-15,k0-7) m2=(n0-7,k8-15) m3=(n8-15,k8-15)
template <int ROWB>
__device__ __forceinline__ uint32_t fragT(uint32_t base, int k0, int nb0, int lane) {
    int r = k0 + ((lane >> 4) & 1) * 8 + (lane & 7);
    int cb = nb0 + ((lane >> 3) & 1) * 16;
    return base + r * ROWB + cb;
}

__device__ __forceinline__ uint32_t packbf2(float lo, float hi) {
    __nv_bfloat162 t = __floats2bfloat162_rn(lo, hi);   // .x = lo (low 16)
    return *(uint32_t*)&t;
}

// ---------------------------------------------------------------------------
// fp32 -> bf16 hi/lo split, row-major
// ---------------------------------------------------------------------------
__global__ __launch_bounds__(256)
void cvt_split(const float* __restrict__ x, __nv_bfloat16* __restrict__ hi,
               __nv_bfloat16* __restrict__ lo) {
    int i = (blockIdx.x * 256 + threadIdx.x) * 4;
    float4 v = *(const float4*)(x + i);
    float vv[4] = {v.x, v.y, v.z, v.w};
#pragma unroll
    for (int j = 0; j < 4; j++) {
        __nv_bfloat16 h = __float2bfloat16(vv[j]);
        hi[i + j] = h;
        lo[i + j] = __float2bfloat16(vv[j] - __bfloat162float(h));
    }
}

// fp32 W[K,N] -> bf16 hi/lo TRANSPOSED [N,K]
__global__ __launch_bounds__(256)
void cvt_splitT(const float* __restrict__ W, __nv_bfloat16* __restrict__ hiT,
                __nv_bfloat16* __restrict__ loT) {
    __shared__ float t[32][33];
    int tx = threadIdx.x, ty = threadIdx.y;
    int n0 = blockIdx.x * 32, k0 = blockIdx.y * 32;
#pragma unroll
    for (int r = 0; r < 4; r++)
        t[ty + r * 8][tx] = W[(size_t)(k0 + ty + r * 8) * Dd + n0 + tx];
    __syncthreads();
#pragma unroll
    for (int r = 0; r < 4; r++) {
        int n = n0 + ty + r * 8;
        int k = k0 + tx;
        float x = t[tx][ty + r * 8];
        __nv_bfloat16 h = __float2bfloat16(x);
        hiT[(size_t)n * Dd + k] = h;
        loT[(size_t)n * Dd + k] = __float2bfloat16(x - __bfloat162float(h));
    }
}

// ---------------------------------------------------------------------------
// bf16-split tensor-core GEMM: C[4096,1024] = A @ B^T (A,B row-major [rows,K])
// MODE 0: fp32 row-major C.
// MODE 2: bf16 hi/lo split-head [bh][s][dk]  (Chi/Clo outputs)
// ---------------------------------------------------------------------------
constexpr int ROW_B = 80;
constexpr int ARR_B = 128 * ROW_B;
constexpr int BUF_B = 4 * ARR_B;
constexpr int GEMM_SMEM_BYTES = 2 * BUF_B;  // 81920

template <int MODE>
__global__ __launch_bounds__(256, 1)
void gemm_bf16split(const __nv_bfloat16* __restrict__ Ahi,
                    const __nv_bfloat16* __restrict__ Alo,
                    const __nv_bfloat16* __restrict__ Bhi,
                    const __nv_bfloat16* __restrict__ Blo,
                    float* __restrict__ C,
                    __nv_bfloat16* __restrict__ Chi,
                    __nv_bfloat16* __restrict__ Clo) {
    extern __shared__ char smem[];
    const uint32_t sbase = smem_u32(smem);
    const int tid = threadIdx.x;
    const int lane = tid & 31;
    const int wid = tid >> 5;
    const int wm = wid >> 2;
    const int wn = wid & 3;
    const int bm = blockIdx.y * 128;
    const int bn = blockIdx.x * 128;

    const __nv_bfloat16* srcs[4] = {Ahi, Alo, Bhi, Blo};

    auto load_chunk = [&](int c, int b) {
        const int k0 = c * 32;
        const uint32_t dst0 = sbase + b * BUF_B;
        const int row = tid >> 1;
#pragma unroll
        for (int a4 = 0; a4 < 4; a4++) {
            const __nv_bfloat16* src = srcs[a4];
            const int rbase = (a4 < 2) ? bm : bn;
            const __nv_bfloat16* gsrc = src + (size_t)(rbase + row) * Dd + k0;
#pragma unroll
            for (int j = 0; j < 2; j++) {
                int cch = (tid & 1) * 2 + j;
                cp16(dst0 + a4 * ARR_B + row * ROW_B + cch * 16, gsrc + cch * 8);
            }
        }
        cp_commit();
    };

    float acc[4][4][4];
#pragma unroll
    for (int i = 0; i < 4; i++)
#pragma unroll
        for (int j = 0; j < 4; j++)
#pragma unroll
            for (int r = 0; r < 4; r++) acc[i][j][r] = 0.0f;

    auto compute = [&](int b) {
        const uint32_t base = sbase + b * BUF_B;
        const uint32_t aHiB = base + 0 * ARR_B;
        const uint32_t aLoB = base + 1 * ARR_B;
        const uint32_t bHiB = base + 2 * ARR_B;
        const uint32_t bLoB = base + 3 * ARR_B;
#pragma unroll
        for (int s = 0; s < 2; s++) {
            const int kb = s * 32;
            uint32_t ahi[4][4], alo[4][4];
#pragma unroll
            for (int i = 0; i < 4; i++) {
                ldm_x4(ahi[i], fragA<ROW_B>(aHiB, wm * 64 + i * 16, kb, lane));
                ldm_x4(alo[i], fragA<ROW_B>(aLoB, wm * 64 + i * 16, kb, lane));
            }
#pragma unroll
            for (int nb = 0; nb < 2; nb++) {
                uint32_t bh[4], bl[4];
                ldm_x4(bh, fragA<ROW_B>(bHiB, wn * 32 + nb * 16, kb, lane));
                ldm_x4(bl, fragA<ROW_B>(bLoB, wn * 32 + nb * 16, kb, lane));
#pragma unroll
                for (int i = 0; i < 4; i++) {
                    mma16816(acc[i][nb * 2 + 0], ahi[i], bh[0], bh[2]);
                    mma16816(acc[i][nb * 2 + 1], ahi[i], bh[1], bh[3]);
                    mma16816(acc[i][nb * 2 + 0], ahi[i], bl[0], bl[2]);
                    mma16816(acc[i][nb * 2 + 1], ahi[i], bl[1], bl[3]);
                    mma16816(acc[i][nb * 2 + 0], alo[i], bh[0], bh[2]);
                    mma16816(acc[i][nb * 2 + 1], alo[i], bh[1], bh[3]);
                }
            }
        }
    };

    constexpr int NCHUNK = Dd / 32;
    load_chunk(0, 0);
    for (int c = 0; c < NCHUNK; c++) {
        if (c + 1 < NCHUNK) {
            load_chunk(c + 1, (c + 1) & 1);
            cp_wait<1>();
        } else {
            cp_wait<0>();
        }
        __syncthreads();
        compute(c & 1);
        __syncthreads();
    }

    const int g = lane >> 2;
    const int tg = lane & 3;
#pragma unroll
    for (int i = 0; i < 4; i++) {
        int r0 = bm + wm * 64 + i * 16 + g;
#pragma unroll
        for (int j = 0; j < 4; j++) {
            int col = bn + wn * 32 + j * 8 + tg * 2;
            if (MODE == 0) {
                *(float2*)(C + (size_t)r0 * Dd + col) =
                    make_float2(acc[i][j][0], acc[i][j][1]);
                *(float2*)(C + (size_t)(r0 + 8) * Dd + col) =
                    make_float2(acc[i][j][2], acc[i][j][3]);
            } else {
                int h = col >> 6, dk = col & 63;
#pragma unroll
                for (int half = 0; half < 2; half++) {
                    int r = r0 + half * 8;
                    int b_ = r >> 11, s = r & 2047;
                    size_t addr = (((size_t)(b_ * Hh + h)) * Ss + s) * DK + dk;
                    float x = acc[i][j][half * 2], y = acc[i][j][half * 2 + 1];
                    __nv_bfloat16 hx = __float2bfloat16(x);
                    __nv_bfloat16 hy = __float2bfloat16(y);
                    *(uint32_t*)(Chi + addr) =
                        packbf2(__bfloat162float(hx), __bfloat162float(hy));
                    *(uint32_t*)(Clo + addr) =
                        packbf2(x - __bfloat162float(hx), y - __bfloat162float(hy));
                }
            }
        }
    }
}

// ---------------------------------------------------------------------------
// Tensor-core flash attention.
// CTA = (head bh, 128 q rows). 8 warps x 16 rows. 128-key tiles, double buffer.
// QK: Qhi*Khi + Qhi*Klo + Qlo*Khi. PV: Phi*Vhi + Phi*Vlo + Plo*Vhi.
// V consumed via ldmatrix.trans from [key][dk] tile. Writes ohi/olo [B,S,D].
// ---------------------------------------------------------------------------
constexpr int AROW = 144;                        // 64 bf16 = 128B + 16 pad
constexpr int QK_TILE_B = 128 * AROW;            // 18432
constexpr int ATT_BUF_B = 4 * QK_TILE_B;         // Khi,Klo,Vhi,Vlo = 73728
constexpr int ATT_SMEM = 2 * QK_TILE_B + 2 * ATT_BUF_B;  // 184320

__global__ __launch_bounds__(256, 1)
void attn_mma() {
    extern __shared__ char smem[];
    const uint32_t sb = smem_u32(smem);
    const int tid = threadIdx.x;
    const int lane = tid & 31;
    const int w = tid >> 5;
    const int bh = blockIdx.y;
    const int qt = blockIdx.x;
    const int b = bh >> 4, h = bh & 15;

    const __nv_bfloat16* Qhg = g_Qh + (size_t)bh * Ss * DK + qt * 128 * DK;
    const __nv_bfloat16* Qlg = g_Ql + (size_t)bh * Ss * DK + qt * 128 * DK;
    const __nv_bfloat16* Khg = g_Kh + (size_t)bh * Ss * DK;
    const __nv_bfloat16* Klg = g_Kl + (size_t)bh * Ss * DK;
    const __nv_bfloat16* Vhg = g_Vh + (size_t)bh * Ss * DK;
    const __nv_bfloat16* Vlg = g_Vl + (size_t)bh * Ss * DK;

    const uint32_t sQh = sb, sQl = sb + QK_TILE_B;

    auto load_kv = [&](int kt, int buf) {
        const uint32_t base = sb + 2 * QK_TILE_B + buf * ATT_BUF_B;
        const __nv_bfloat16* gk[4] = {Khg, Klg, Vhg, Vlg};
#pragma unroll
        for (int a4 = 0; a4 < 4; a4++) {
            const __nv_bfloat16* src = gk[a4] + (size_t)kt * 128 * DK;
#pragma unroll
            for (int p = 0; p < 4; p++) {
                int idx = tid + p * 256;      // 0..1023
                int r = idx >> 3, c = idx & 7;
                cp16(base + a4 * QK_TILE_B + r * AROW + c * 16, src + r * DK + c * 8);
            }
        }
        cp_commit();
    };

    // Q tiles (hi/lo) + tile 0 as first group
    {
#pragma unroll
        for (int p = 0; p < 4; p++) {
            int idx = tid + p * 256;
            int r = idx >> 3, c = idx & 7;
            cp16(sQh + r * AROW + c * 16, Qhg + r * DK + c * 8);
            cp16(sQl + r * AROW + c * 16, Qlg + r * DK + c * 8);
        }
    }
    load_kv(0, 0);
    cp_wait<0>();
    __syncthreads();

    // preload Q fragments (4 k16 steps over dk)
    uint32_t qhf[4][4], qlf[4][4];
#pragma unroll
    for (int s = 0; s < 4; s++) {
        ldm_x4(qhf[s], fragA<AROW>(sQh, w * 16, s * 32, lane));
        ldm_x4(qlf[s], fragA<AROW>(sQl, w * 16, s * 32, lane));
    }

    float m0 = -1e30f, m1 = -1e30f, l0 = 0.0f, l1 = 0.0f;
    float Oacc[8][4];
#pragma unroll
    for (int j = 0; j < 8; j++)
#pragma unroll
        for (int r = 0; r < 4; r++) Oacc[j][r] = 0.0f;

    constexpr int NT = Ss / 128;   // 16
    for (int kt = 0; kt < NT; kt++) {
        if (kt + 1 < NT) {
            load_kv(kt + 1, (kt + 1) & 1);
            cp_wait<1>();
        } else {
            cp_wait<0>();
        }
        __syncthreads();

        const uint32_t base = sb + 2 * QK_TILE_B + (kt & 1) * ATT_BUF_B;
        const uint32_t kHi = base, kLo = base + QK_TILE_B;
        const uint32_t vHi = base + 2 * QK_TILE_B, vLo = base + 3 * QK_TILE_B;

        // ---- S = Q K^T (fp32 acc), 16x128 per warp
        float sfr[16][4];
#pragma unroll
        for (int j = 0; j < 16; j++)
#pragma unroll
            for (int r = 0; r < 4; r++) sfr[j][r] = 0.0f;

#pragma unroll
        for (int s = 0; s < 4; s++) {          // dk k16 steps
            const int kb = s * 32;
#pragma unroll
            for (int nb = 0; nb < 8; nb++) {   // key n16 blocks
                uint32_t bh4[4], bl4[4];
                ldm_x4(bh4, fragA<AROW>(kHi, nb * 16, kb, lane));
                ldm_x4(bl4, fragA<AROW>(kLo, nb * 16, kb, lane));
                mma16816(sfr[nb * 2 + 0], qhf[s], bh4[0], bh4[2]);
                mma16816(sfr[nb * 2 + 1], qhf[s], bh4[1], bh4[3]);
                mma16816(sfr[nb * 2 + 0], qhf[s], bl4[0], bl4[2]);
                mma16816(sfr[nb * 2 + 1], qhf[s], bl4[1], bl4[3]);
                mma16816(sfr[nb * 2 + 0], qlf[s], bh4[0], bh4[2]);
                mma16816(sfr[nb * 2 + 1], qlf[s], bh4[1], bh4[3]);
            }
        }

        // ---- online softmax (fold SCALE into exp arg)
        float mt0 = m0, mt1 = m1;
#pragma unroll
        for (int j = 0; j < 16; j++) {
            mt0 = fmaxf(mt0, fmaxf(sfr[j][0], sfr[j][1]));
            mt1 = fmaxf(mt1, fmaxf(sfr[j][2], sfr[j][3]));
        }
        mt0 = fmaxf(mt0, __shfl_xor_sync(0xffffffffu, mt0, 1));
        mt0 = fmaxf(mt0, __shfl_xor_sync(0xffffffffu, mt0, 2));
        mt1 = fmaxf(mt1, __shfl_xor_sync(0xffffffffu, mt1, 1));
        mt1 = fmaxf(mt1, __shfl_xor_sync(0xffffffffu, mt1, 2));

        const float al0 = __expf((m0 - mt0) * SCALE);
        const float al1 = __expf((m1 - mt1) * SCALE);
        m0 = mt0; m1 = mt1;

        float rs0 = 0.0f, rs1 = 0.0f;
#pragma unroll
        for (int j = 0; j < 16; j++) {
            sfr[j][0] = __expf((sfr[j][0] - m0) * SCALE);
            sfr[j][1] = __expf((sfr[j][1] - m0) * SCALE);
            sfr[j][2] = __expf((sfr[j][2] - m1) * SCALE);
            sfr[j][3] = __expf((sfr[j][3] - m1) * SCALE);
            rs0 += sfr[j][0] + sfr[j][1];
            rs1 += sfr[j][2] + sfr[j][3];
        }
        rs0 += __shfl_xor_sync(0xffffffffu, rs0, 1);
        rs0 += __shfl_xor_sync(0xffffffffu, rs0, 2);
        rs1 += __shfl_xor_sync(0xffffffffu, rs1, 1);
        rs1 += __shfl_xor_sync(0xffffffffu, rs1, 2);
        l0 = l0 * al0 + rs0;
        l1 = l1 * al1 + rs1;
#pragma unroll
        for (int j = 0; j < 8; j++) {
            Oacc[j][0] *= al0;
            Oacc[j][1] *= al0;
            Oacc[j][2] *= al1;
            Oacc[j][3] *= al1;
        }

        // ---- O += P V, P packed in regs from S frags
#pragma unroll
        for (int st = 0; st < 8; st++) {       // key k16 steps
            uint32_t ph[4], pl[4];
#pragma unroll
            for (int q = 0; q < 2; q++) {      // frag 2st+q
                const float* f = sfr[2 * st + q];
#pragma unroll
                for (int hv = 0; hv < 2; hv++) {
                    float x = f[hv * 2], y = f[hv * 2 + 1];
                    __nv_bfloat16 hx = __float2bfloat16(x);
                    __nv_bfloat16 hy = __float2bfloat16(y);
                    ph[q * 2 + hv] =
                        packbf2(__bfloat162float(hx), __bfloat162float(hy));
                    pl[q * 2 + hv] =
                        packbf2(x - __bfloat162float(hx), y - __bfloat162float(hy));
                }
            }
            // NOTE frag order: a0=(row g,k0-7)=f0 regs01 ; a1=(g+8,k0-7)=f0 regs23 ;
            //                  a2=(g,k8-15)=f1 regs01 ; a3=(g+8,k8-15)=f1 regs23
            uint32_t pa_h[4] = {ph[0], ph[1], ph[2], ph[3]};
            uint32_t pa_l[4] = {pl[0], pl[1], pl[2], pl[3]};

#pragma unroll
            for (int nb = 0; nb < 4; nb++) {   // dk n16 blocks
                uint32_t vh4[4], vl4[4];
                ldm_x4_t(vh4, fragT<AROW>(vHi, st * 16, nb * 32, lane));
                ldm_x4_t(vl4, fragT<AROW>(vLo, st * 16, nb * 32, lane));
                mma16816(Oacc[nb * 2 + 0], pa_h, vh4[0], vh4[2]);
                mma16816(Oacc[nb * 2 + 1], pa_h, vh4[1], vh4[3]);
                mma16816(Oacc[nb * 2 + 0], pa_h, vl4[0], vl4[2]);
                mma16816(Oacc[nb * 2 + 1], pa_h, vl4[1], vl4[3]);
                mma16816(Oacc[nb * 2 + 0], pa_l, vh4[0], vh4[2]);
                mma16816(Oacc[nb * 2 + 1], pa_l, vh4[1], vh4[3]);
            }
        }
        __syncthreads();
    }

    // ---- epilogue: normalize, split to bf16 hi/lo, write [B,S,D]
    const float inv0 = 1.0f / l0;
    const float inv1 = 1.0f / l1;
    const int g = lane >> 2;
    const int t = lane & 3;
    const int row0 = qt * 128 + w * 16 + g;
    const size_t gbase0 = ((size_t)b * Ss + row0) * Dd + h * 64;
    const size_t gbase1 = gbase0 + 8 * Dd;
#pragma unroll
    for (int j = 0; j < 8; j++) {
        int col = j * 8 + t * 2;
        float o00 = Oacc[j][0] * inv0, o01 = Oacc[j][1] * inv0;
        float o10 = Oacc[j][2] * inv1, o11 = Oacc[j][3] * inv1;
        __nv_bfloat16 h00 = __float2bfloat16(o00), h01 = __float2bfloat16(o01);
        __nv_bfloat16 h10 = __float2bfloat16(o10), h11 = __float2bfloat16(o11);
        *(uint32_t*)(g_ohi + gbase0 + col) =
            packbf2(__bfloat162float(h00), __bfloat162float(h01));
        *(uint32_t*)(g_olo + gbase0 + col) =
            packbf2(o00 - __bfloat162float(h00), o01 - __bfloat162float(h01));
        *(uint32_t*)(g_ohi + gbase1 + col) =
            packbf2(__bfloat162float(h10), __bfloat162float(h11));
        *(uint32_t*)(g_olo + gbase1 + col) =
            packbf2(o10 - __bfloat162float(h10), o11 - __bfloat162float(h11));
    }
}

// ---------------------------------------------------------------------------
// Launch
// ---------------------------------------------------------------------------
extern "C" void kernel_launch(void* const* d_in, const int* in_sizes, int n_in,
                              void* d_out, int out_size) {
    const float* q  = (const float*)d_in[0];
    const float* k  = (const float*)d_in[1];
    const float* v  = (const float*)d_in[2];
    const float* Wq = (const float*)d_in[3];
    const float* Wk = (const float*)d_in[4];
    const float* Wv = (const float*)d_in[5];
    const float* Wo = (const float*)d_in[6];
    float* out = (float*)d_out;

    __nv_bfloat16 *qhi, *qlo, *khi, *klo, *vhi, *vlo, *ohi, *olo, *whi, *wlo;
    __nv_bfloat16 *Qh, *Ql, *Kh, *Kl, *Vh, *Vl;
    cudaGetSymbolAddress((void**)&qhi, g_qhi);
    cudaGetSymbolAddress((void**)&qlo, g_qlo);
    cudaGetSymbolAddress((void**)&khi, g_khi);
    cudaGetSymbolAddress((void**)&klo, g_klo);
    cudaGetSymbolAddress((void**)&vhi, g_vhi);
    cudaGetSymbolAddress((void**)&vlo, g_vlo);
    cudaGetSymbolAddress((void**)&ohi, g_ohi);
    cudaGetSymbolAddress((void**)&olo, g_olo);
    cudaGetSymbolAddress((void**)&whi, g_whi);
    cudaGetSymbolAddress((void**)&wlo, g_wlo);
    cudaGetSymbolAddress((void**)&Qh, g_Qh);
    cudaGetSymbolAddress((void**)&Ql, g_Ql);
    cudaGetSymbolAddress((void**)&Kh, g_Kh);
    cudaGetSymbolAddress((void**)&Kl, g_Kl);
    cudaGetSymbolAddress((void**)&Vh, g_Vh);
    cudaGetSymbolAddress((void**)&Vl, g_Vl);
    const size_t WSTRIDE = (size_t)Dd * Dd;

    cudaFuncSetAttribute(attn_mma,
                         cudaFuncAttributeMaxDynamicSharedMemorySize, ATT_SMEM);
    cudaFuncSetAttribute(gemm_bf16split<0>,
                         cudaFuncAttributeMaxDynamicSharedMemorySize, GEMM_SMEM_BYTES);
    cudaFuncSetAttribute(gemm_bf16split<2>,
                         cudaFuncAttributeMaxDynamicSharedMemorySize, GEMM_SMEM_BYTES);

    const int cvt_blocks = Mrows * Dd / (256 * 4);
    cvt_split<<<cvt_blocks, 256>>>(q, qhi, qlo);
    cvt_split<<<cvt_blocks, 256>>>(k, khi, klo);
    cvt_split<<<cvt_blocks, 256>>>(v, vhi, vlo);

    dim3 tB(32, 8), tG(Dd / 32, Dd / 32);
    cvt_splitT<<<tG, tB>>>(Wq, whi + 0 * WSTRIDE, wlo + 0 * WSTRIDE);
    cvt_splitT<<<tG, tB>>>(Wk, whi + 1 * WSTRIDE, wlo + 1 * WSTRIDE);
    cvt_splitT<<<tG, tB>>>(Wv, whi + 2 * WSTRIDE, wlo + 2 * WSTRIDE);
    cvt_splitT<<<tG, tB>>>(Wo, whi + 3 * WSTRIDE, wlo + 3 * WSTRIDE);

    dim3 gg(Dd / 128, Mrows / 128);
    gemm_bf16split<2><<<gg, 256, GEMM_SMEM_BYTES>>>(
        qhi, qlo, whi + 0 * WSTRIDE, wlo + 0 * WSTRIDE, nullptr, Qh, Ql);
    gemm_bf16split<2><<<gg, 256, GEMM_SMEM_BYTES>>>(
        khi, klo, whi + 1 * WSTRIDE, wlo + 1 * WSTRIDE, nullptr, Kh, Kl);
    gemm_bf16split<2><<<gg, 256, GEMM_SMEM_BYTES>>>(
        vhi, vlo, whi + 2 * WSTRIDE, wlo + 2 * WSTRIDE, nullptr, Vh, Vl);

    attn_mma<<<dim3(Ss / 128, Bb * Hh), 256, ATT_SMEM>>>();

    gemm_bf16split<0><<<gg, 256, GEMM_SMEM_BYTES>>>(
        ohi, olo, whi + 3 * WSTRIDE, wlo + 3 * WSTRIDE, out, nullptr, nullptr);
}